// round 2
// baseline (speedup 1.0000x reference)
#include <cuda_runtime.h>
#include <math.h>

// Problem shape (fixed by the dataset)
#define Bn 16
#define Qn 300
#define Tn 50
#define Cn 80          // NUM_CLASSES
#define Hn 128
#define Wn 128
#define NJ (Bn*Tn)     // 800 matched pairs / positives
#define HM_ELEMS (Bn*Cn*Hn*Wn)   // 20,971,520
#define HASHN 2048

// Global accumulators (device globals: no allocation allowed)
__device__ double g_hm;        // focal sum (base + corrections)
__device__ double g_boxc;      // box-map L1 correction sum
__device__ double g_ce_num;    // sum cw*nll
__device__ double g_ce_den;    // sum cw
__device__ double g_bbox;      // L1 box loss sum
__device__ double g_giou;      // sum (1 - giou)
__device__ int    g_numpos;    // unique (b,gy,gx) count

// ---------------------------------------------------------------------------
// Prep kernel: single block.
//  - zeroes accumulators
//  - computes normalized cxcywh target boxes
//  - dedupes positive positions (hash in shared), focal correction at positives
//  - last-wins winner per (b,gy,gx) cell -> box_map L1 correction
//  - matched-pair L1 + GIoU losses
// ---------------------------------------------------------------------------
__global__ void k_prep(const float* __restrict__ pred_boxes,
                       const float* __restrict__ hm,
                       const float* __restrict__ box_map,
                       const float* __restrict__ tgt_boxes,
                       const int*   __restrict__ tgt_labels,
                       const float* __restrict__ tgt_sizes,
                       const int*   __restrict__ src_idx,
                       const int*   __restrict__ tgt_idx)
{
    __shared__ float bfs[NJ][4];
    __shared__ int   key3s[NJ];
    __shared__ int   hashA[HASHN];    // dedupe (b,label,gy,gx)
    __shared__ int   hashBk[HASHN];   // keys   (b,gy,gx)
    __shared__ int   hashBv[HASHN];   // max j per key (last-wins winner)
    __shared__ int   snum;
    __shared__ float rHm[32], rBox[32], rBb[32], rGi[32];

    const int tid = threadIdx.x;
    if (tid == 0) {
        g_hm = 0.0; g_boxc = 0.0; g_ce_num = 0.0; g_ce_den = 0.0;
        g_bbox = 0.0; g_giou = 0.0; g_numpos = 0;
        snum = 0;
    }
    for (int i = tid; i < HASHN; i += blockDim.x) {
        hashA[i] = -1; hashBk[i] = -1; hashBv[i] = -1;
    }
    __syncthreads();

    float myHm = 0.f, myBox = 0.f, myBb = 0.f, myGi = 0.f;
    const int j = tid;
    int b = 0, lf = 0, gx = 0, gy = 0;

    if (j < NJ) {
        b = j / Tn;
        const float h_im = tgt_sizes[b*2 + 0];
        const float w_im = tgt_sizes[b*2 + 1];
        const float* tb = tgt_boxes + j*4;
        float x1 = tb[0] / w_im, y1 = tb[1] / h_im;
        float x2 = tb[2] / w_im, y2 = tb[3] / h_im;
        float cx = (x1 + x2) * 0.5f, cy = (y1 + y2) * 0.5f;
        float bw = x2 - x1,          bh = y2 - y1;
        bfs[j][0] = cx; bfs[j][1] = cy; bfs[j][2] = bw; bfs[j][3] = bh;

        lf = tgt_labels[j];
        gx = min(max((int)(cx * (float)Wn), 0), Wn - 1);
        gy = min(max((int)(cy * (float)Hn), 0), Hn - 1);
        const int key3 = (b*Hn + gy)*Wn + gx;
        key3s[j] = key3;
        const int key4 = ((b*Cn + lf)*Hn + gy)*Wn + gx;

        // ---- hashA: dedupe positives; representative computes focal delta ----
        unsigned hh = ((unsigned)key4 * 2654435761u) & (HASHN - 1);
        bool ins = false;
        for (;;) {
            int prev = atomicCAS(&hashA[hh], -1, key4);
            if (prev == -1) { ins = true; break; }
            if (prev == key4) break;
            hh = (hh + 1) & (HASHN - 1);
        }
        if (ins) {
            const float x  = hm[key4];
            const float ax = fabsf(x);
            const float l1p = log1pf(expf(-ax));
            const float ce1 = fmaxf(x, 0.f) - x + l1p;   // target = 1
            const float ce0 = fmaxf(x, 0.f) + l1p;       // target = 0
            const float p   = 1.f / (1.f + expf(-x));
            const float l1  = 0.25f * (1.f - p) * (1.f - p) * ce1;
            const float l0  = 0.75f * p * p * ce0;
            myHm += l1 - l0;
        }

        // ---- hashB: last-wins winner per (b,gy,gx); count unique cells ----
        hh = ((unsigned)key3 * 2654435761u) & (HASHN - 1);
        int slot;
        for (;;) {
            int prev = atomicCAS(&hashBk[hh], -1, key3);
            if (prev == -1) { atomicAdd(&snum, 1); slot = hh; break; }
            if (prev == key3) { slot = hh; break; }
            hh = (hh + 1) & (HASHN - 1);
        }
        atomicMax(&hashBv[slot], j);
    }
    __syncthreads();

    if (j < NJ) {
        // box_map correction: only the winning (last) writer of each cell counts
        const int key3 = key3s[j];
        unsigned hh = ((unsigned)key3 * 2654435761u) & (HASHN - 1);
        while (hashBk[hh] != key3) hh = (hh + 1) & (HASHN - 1);
        if (hashBv[hh] == j) {
            #pragma unroll
            for (int c = 0; c < 4; c++) {
                const float bm = box_map[((b*4 + c)*Hn + gy)*Wn + gx];
                myBox += fabsf(bm - bfs[j][c]);
            }
        }

        // matched pair: L1 + GIoU
        const int t  = j % Tn;  (void)t;
        const int si = src_idx[j];
        const int ti = tgt_idx[j];
        const float* sb = pred_boxes + (b*Qn + si)*4;
        const float s0 = sb[0], s1 = sb[1], s2 = sb[2], s3 = sb[3];
        const float* mb = bfs[b*Tn + ti];
        const float m0 = mb[0], m1 = mb[1], m2 = mb[2], m3 = mb[3];

        myBb += fabsf(s0 - m0) + fabsf(s1 - m1) + fabsf(s2 - m2) + fabsf(s3 - m3);

        const float ax1 = s0 - 0.5f*s2, ay1 = s1 - 0.5f*s3;
        const float ax2 = s0 + 0.5f*s2, ay2 = s1 + 0.5f*s3;
        const float bx1 = m0 - 0.5f*m2, by1 = m1 - 0.5f*m3;
        const float bx2 = m0 + 0.5f*m2, by2 = m1 + 0.5f*m3;
        const float area_a = (ax2 - ax1) * (ay2 - ay1);
        const float area_b = (bx2 - bx1) * (by2 - by1);
        const float iw = fmaxf(fminf(ax2, bx2) - fmaxf(ax1, bx1), 0.f);
        const float ih = fmaxf(fminf(ay2, by2) - fmaxf(ay1, by1), 0.f);
        const float inter = iw * ih;
        const float uni   = area_a + area_b - inter;
        const float iou   = inter / uni;
        const float cw_   = fmaxf(fmaxf(ax2, bx2) - fminf(ax1, bx1), 0.f);
        const float ch_   = fmaxf(fmaxf(ay2, by2) - fminf(ay1, by1), 0.f);
        const float ac    = cw_ * ch_;
        const float giou  = iou - (ac - uni) / ac;
        myGi += 1.f - giou;
    }

    // block reduction of the 4 partials
    const int lane = tid & 31, wrp = tid >> 5;
    #pragma unroll
    for (int o = 16; o; o >>= 1) {
        myHm  += __shfl_xor_sync(0xffffffffu, myHm,  o);
        myBox += __shfl_xor_sync(0xffffffffu, myBox, o);
        myBb  += __shfl_xor_sync(0xffffffffu, myBb,  o);
        myGi  += __shfl_xor_sync(0xffffffffu, myGi,  o);
    }
    if (lane == 0) { rHm[wrp] = myHm; rBox[wrp] = myBox; rBb[wrp] = myBb; rGi[wrp] = myGi; }
    __syncthreads();
    if (tid == 0) {
        double a = 0, bb2 = 0, c = 0, d = 0;
        const int nw = blockDim.x >> 5;
        for (int i = 0; i < nw; i++) { a += rHm[i]; bb2 += rBox[i]; c += rBb[i]; d += rGi[i]; }
        g_hm   = a;      // focal kernel adds on top later
        g_boxc = bb2;
        g_bbox = c;
        g_giou = d;
        g_numpos = snum;
    }
}

// ---------------------------------------------------------------------------
// Focal base sum over all heatmap elements assuming target=0:
//   loss0 = 0.75 * sigmoid(x)^2 * softplus(x)
// ---------------------------------------------------------------------------
__device__ __forceinline__ float floss0(float x) {
    const float u = __expf(x);                  // e^x  (|x| <~ 6, safe)
    const float r = __fdividef(1.f, 1.f + u);   // 1/(1+e^x)
    const float p = u * r;                      // sigmoid(x)
    const float ce = -__logf(r);                // log(1+e^x) = softplus(x)
    return 0.75f * p * p * ce;
}

__global__ void k_focal(const float4* __restrict__ hm4, int n4) {
    float s = 0.f;
    const int stride = gridDim.x * blockDim.x;
    int i = blockIdx.x * blockDim.x + threadIdx.x;
    for (; i + 3*stride < n4; i += 4*stride) {
        const float4 a = hm4[i];
        const float4 b = hm4[i + stride];
        const float4 c = hm4[i + 2*stride];
        const float4 d = hm4[i + 3*stride];
        s += floss0(a.x) + floss0(a.y) + floss0(a.z) + floss0(a.w);
        s += floss0(b.x) + floss0(b.y) + floss0(b.z) + floss0(b.w);
        s += floss0(c.x) + floss0(c.y) + floss0(c.z) + floss0(c.w);
        s += floss0(d.x) + floss0(d.y) + floss0(d.z) + floss0(d.w);
    }
    for (; i < n4; i += stride) {
        const float4 a = hm4[i];
        s += floss0(a.x) + floss0(a.y) + floss0(a.z) + floss0(a.w);
    }

    // block reduce
    __shared__ float red[32];
    const int lane = threadIdx.x & 31, wrp = threadIdx.x >> 5;
    #pragma unroll
    for (int o = 16; o; o >>= 1) s += __shfl_xor_sync(0xffffffffu, s, o);
    if (lane == 0) red[wrp] = s;
    __syncthreads();
    if (wrp == 0) {
        float v = (lane < (blockDim.x >> 5)) ? red[lane] : 0.f;
        #pragma unroll
        for (int o = 16; o; o >>= 1) v += __shfl_xor_sync(0xffffffffu, v, o);
        if (lane == 0) atomicAdd(&g_hm, (double)v);
    }
}

// ---------------------------------------------------------------------------
// Weighted CE over log_softmax rows (B*Q rows of 81 logits).
// 64 blocks: block = (batch, quarter of 300 rows). Warp per row.
// ---------------------------------------------------------------------------
__global__ void k_ce(const float* __restrict__ logits,
                     const int*   __restrict__ tgt_labels,
                     const int*   __restrict__ src_idx,
                     const int*   __restrict__ tgt_idx,
                     const float* __restrict__ empty_weight)
{
    __shared__ int   tc[Qn];
    __shared__ float rn[8], rd[8];
    const int b   = blockIdx.x >> 2;
    const int seg = blockIdx.x & 3;
    const int tid = threadIdx.x;

    for (int i = tid; i < Qn; i += blockDim.x) tc[i] = Cn;   // "no object"
    __syncthreads();
    if (tid < Tn) {
        const int s = src_idx[b*Tn + tid];
        tc[s] = tgt_labels[b*Tn + tgt_idx[b*Tn + tid]];
    }
    __syncthreads();

    const int wrp = tid >> 5, lane = tid & 31;
    float num = 0.f, den = 0.f;
    for (int q = seg*75 + wrp; q < seg*75 + 75; q += 8) {
        const float* row = logits + (size_t)(b*Qn + q) * (Cn + 1);
        const float x0 = row[lane];
        const float x1 = row[lane + 32];
        const float x2 = (lane < 17) ? row[lane + 64] : -3.4e38f;
        float mx = fmaxf(fmaxf(x0, x1), x2);
        #pragma unroll
        for (int o = 16; o; o >>= 1) mx = fmaxf(mx, __shfl_xor_sync(0xffffffffu, mx, o));
        float se = __expf(x0 - mx) + __expf(x1 - mx) + ((lane < 17) ? __expf(x2 - mx) : 0.f);
        #pragma unroll
        for (int o = 16; o; o >>= 1) se += __shfl_xor_sync(0xffffffffu, se, o);
        if (lane == 0) {
            const int t = tc[q];
            const float nll = mx + __logf(se) - row[t];
            const float cw  = empty_weight[t];
            num += cw * nll;
            den += cw;
        }
    }
    if (lane == 0) { rn[wrp] = num; rd[wrp] = den; }
    __syncthreads();
    if (tid == 0) {
        double a = 0, c = 0;
        for (int i = 0; i < 8; i++) { a += rn[i]; c += rd[i]; }
        atomicAdd(&g_ce_num, a);
        atomicAdd(&g_ce_den, c);
    }
}

// ---------------------------------------------------------------------------
// Combine -> 5 outputs
// ---------------------------------------------------------------------------
__global__ void k_final(float* __restrict__ out) {
    const float num_boxes = (float)NJ;  // B*T = 800
    const float ce   = (float)(g_ce_num / g_ce_den);
    const float bbox = (float)g_bbox / num_boxes;
    const float giou = (float)g_giou / num_boxes;
    const float np   = fmaxf((float)g_numpos, 1.f);
    const float hm   = (float)(g_hm)   / np;
    const float bl   = (float)(g_boxc) / np;
    const float aux  = 1.f * hm + 5.f * bl;           // AUX_HM_W*hm + AUX_BOX_W*box
    const float tot  = 1.f * ce + 5.f * bbox + 2.f * giou + 1.f * aux;
    out[0] = ce; out[1] = bbox; out[2] = giou; out[3] = aux; out[4] = tot;
}

extern "C" void kernel_launch(void* const* d_in, const int* in_sizes, int n_in,
                              void* d_out, int out_size)
{
    const float* pred_logits  = (const float*)d_in[0];
    const float* pred_boxes   = (const float*)d_in[1];
    const float* heatmap      = (const float*)d_in[2];
    const float* box_map      = (const float*)d_in[3];
    const float* tgt_boxes    = (const float*)d_in[4];
    const int*   tgt_labels   = (const int*)  d_in[5];
    const float* tgt_sizes    = (const float*)d_in[6];
    const int*   src_idx      = (const int*)  d_in[7];
    const int*   tgt_idx      = (const int*)  d_in[8];
    const float* empty_weight = (const float*)d_in[9];

    k_prep<<<1, 1024>>>(pred_boxes, heatmap, box_map, tgt_boxes,
                        tgt_labels, tgt_sizes, src_idx, tgt_idx);
    k_focal<<<1184, 256>>>((const float4*)heatmap, HM_ELEMS / 4);
    k_ce<<<64, 256>>>(pred_logits, tgt_labels, src_idx, tgt_idx, empty_weight);
    k_final<<<1, 1>>>((float*)d_out);
}

// round 3
// speedup vs baseline: 1.3615x; 1.3615x over previous
#include <cuda_runtime.h>
#include <math.h>

// Problem shape (fixed by the dataset)
#define Bn 16
#define Qn 300
#define Tn 50
#define Cn 80          // NUM_CLASSES
#define Hn 128
#define Wn 128
#define NJ (Bn*Tn)                 // 800
#define HM_ELEMS (Bn*Cn*Hn*Wn)     // 20,971,520
#define HM4 (HM_ELEMS/4)           // 5,242,880
#define HASHN 2048
#define G  296                     // grid size (2 blocks/SM on 148 SMs)
#define BT 512                     // block size
#define NW (BT/32)                 // 16 warps

// Per-block partial slots (overwritten every launch -> no zeroing needed)
__device__ double p_hm[G], p_cn[G], p_cd[G];
__device__ double p_box, p_bb, p_gi;
__device__ int    p_np;
__device__ unsigned g_arrive = 0;   // self-wrapping arrival counter

struct PrepSh {
    float bfs[NJ][4];
    int   key3s[NJ];
    int   hashA[HASHN];   // dedupe (b,label,gy,gx)
    int   hashBk[HASHN];  // keys   (b,gy,gx)
    int   hashBv[HASHN];  // last-wins winner j per key
    int   snum;
};
struct CeSh { int tc[Qn]; };
union ShU { PrepSh prep; CeSh ce; };

// focal loss at target==0: 0.75 * sigmoid(x)^2 * softplus(x)
__device__ __forceinline__ float floss0(float x) {
    const float u  = __expf(x);                  // e^x (|x| small, safe)
    const float r  = __fdividef(1.f, 1.f + u);   // 1/(1+e^x)
    const float p  = u * r;                      // sigmoid(x)
    const float ce = -__logf(r);                 // softplus(x)
    return 0.75f * p * p * ce;
}

__global__ void __launch_bounds__(BT, 2)
k_all(const float*  __restrict__ pred_logits,
      const float*  __restrict__ pred_boxes,
      const float4* __restrict__ hm4,
      const float*  __restrict__ hm,
      const float*  __restrict__ box_map,
      const float*  __restrict__ tgt_boxes,
      const int*    __restrict__ tgt_labels,
      const float*  __restrict__ tgt_sizes,
      const int*    __restrict__ src_idx,
      const int*    __restrict__ tgt_idx,
      const float*  __restrict__ empty_weight,
      float* __restrict__ out)
{
    __shared__ ShU    sh;
    __shared__ float  redf[NW][6];
    __shared__ double redd[NW][3];
    __shared__ bool   isLast;

    const int tid  = threadIdx.x;
    const int bid  = blockIdx.x;
    const int lane = tid & 31, wrp = tid >> 5;

    float corr = 0.f, myBox = 0.f, myBb = 0.f, myGi = 0.f;
    float ceN = 0.f, ceD = 0.f;

    // ======================= block 0: prep (overlapped) =======================
    if (bid == 0) {
        for (int i = tid; i < HASHN; i += BT) {
            sh.prep.hashA[i] = -1; sh.prep.hashBk[i] = -1; sh.prep.hashBv[i] = -1;
        }
        if (tid == 0) sh.prep.snum = 0;
        __syncthreads();

        // phase 1: normalized boxes + hash inserts + focal corrections
        for (int j = tid; j < NJ; j += BT) {
            const int b = j / Tn;
            const float h_im = tgt_sizes[b*2 + 0];
            const float w_im = tgt_sizes[b*2 + 1];
            const float4 tb = ((const float4*)tgt_boxes)[j];
            const float x1 = tb.x / w_im, y1 = tb.y / h_im;
            const float x2 = tb.z / w_im, y2 = tb.w / h_im;
            const float cx = 0.5f*(x1 + x2), cy = 0.5f*(y1 + y2);
            sh.prep.bfs[j][0] = cx;     sh.prep.bfs[j][1] = cy;
            sh.prep.bfs[j][2] = x2 - x1; sh.prep.bfs[j][3] = y2 - y1;

            const int lf = tgt_labels[j];
            const int gx = min(max((int)(cx * (float)Wn), 0), Wn - 1);
            const int gy = min(max((int)(cy * (float)Hn), 0), Hn - 1);
            const int key3 = (b*Hn + gy)*Wn + gx;
            sh.prep.key3s[j] = key3;
            const int key4 = ((b*Cn + lf)*Hn + gy)*Wn + gx;

            // dedupe positives; representative computes exact focal delta
            unsigned hh = ((unsigned)key4 * 2654435761u) & (HASHN - 1);
            bool ins = false;
            for (;;) {
                int prev = atomicCAS(&sh.prep.hashA[hh], -1, key4);
                if (prev == -1) { ins = true; break; }
                if (prev == key4) break;
                hh = (hh + 1) & (HASHN - 1);
            }
            if (ins) {
                const float x   = hm[key4];
                const float ax  = fabsf(x);
                const float l1p = log1pf(expf(-ax));
                const float ce1 = fmaxf(x, 0.f) - x + l1p;   // target = 1
                const float ce0 = fmaxf(x, 0.f) + l1p;       // target = 0
                const float pr  = 1.f / (1.f + expf(-x));
                const float l1  = 0.25f * (1.f - pr) * (1.f - pr) * ce1;
                const float l0  = 0.75f * pr * pr * ce0;
                corr += l1 - l0;
            }

            // last-wins winner per (b,gy,gx)
            hh = ((unsigned)key3 * 2654435761u) & (HASHN - 1);
            int slot;
            for (;;) {
                int prev = atomicCAS(&sh.prep.hashBk[hh], -1, key3);
                if (prev == -1) { atomicAdd(&sh.prep.snum, 1); slot = hh; break; }
                if (prev == key3) { slot = hh; break; }
                hh = (hh + 1) & (HASHN - 1);
            }
            atomicMax(&sh.prep.hashBv[slot], j);
        }
        __syncthreads();

        // phase 2: box_map correction (winners only) + pair L1 + GIoU
        for (int j = tid; j < NJ; j += BT) {
            const int b    = j / Tn;
            const int key3 = sh.prep.key3s[j];
            const int gx   = key3 & (Wn - 1);
            const int gy   = (key3 >> 7) & (Hn - 1);

            unsigned hh = ((unsigned)key3 * 2654435761u) & (HASHN - 1);
            while (sh.prep.hashBk[hh] != key3) hh = (hh + 1) & (HASHN - 1);
            if (sh.prep.hashBv[hh] == j) {
                #pragma unroll
                for (int c = 0; c < 4; c++) {
                    const float bm = box_map[((b*4 + c)*Hn + gy)*Wn + gx];
                    myBox += fabsf(bm - sh.prep.bfs[j][c]);
                }
            }

            const int si = src_idx[j];
            const int ti = tgt_idx[j];
            const float4 sb = ((const float4*)pred_boxes)[b*Qn + si];
            const float s0 = sb.x, s1 = sb.y, s2 = sb.z, s3 = sb.w;
            const float* mb = sh.prep.bfs[b*Tn + ti];
            const float m0 = mb[0], m1 = mb[1], m2 = mb[2], m3 = mb[3];

            myBb += fabsf(s0-m0) + fabsf(s1-m1) + fabsf(s2-m2) + fabsf(s3-m3);

            const float ax1 = s0 - 0.5f*s2, ay1 = s1 - 0.5f*s3;
            const float ax2 = s0 + 0.5f*s2, ay2 = s1 + 0.5f*s3;
            const float bx1 = m0 - 0.5f*m2, by1 = m1 - 0.5f*m3;
            const float bx2 = m0 + 0.5f*m2, by2 = m1 + 0.5f*m3;
            const float area_a = (ax2-ax1)*(ay2-ay1);
            const float area_b = (bx2-bx1)*(by2-by1);
            const float iw = fmaxf(fminf(ax2,bx2) - fmaxf(ax1,bx1), 0.f);
            const float ih = fmaxf(fminf(ay2,by2) - fmaxf(ay1,by1), 0.f);
            const float inter = iw*ih;
            const float uni   = area_a + area_b - inter;
            const float iou   = inter / uni;
            const float cw_   = fmaxf(fmaxf(ax2,bx2) - fminf(ax1,bx1), 0.f);
            const float ch_   = fmaxf(fmaxf(ay2,by2) - fminf(ay1,by1), 0.f);
            const float ac    = cw_ * ch_;
            myGi += 1.f - (iou - (ac - uni)/ac);
        }
        if (tid == 0) p_np = sh.prep.snum;
    }
    // ======================= blocks 1..64: weighted CE =======================
    else if (bid <= 64) {
        const int idx = bid - 1;
        const int b   = idx >> 2;
        const int seg = idx & 3;
        for (int i = tid; i < Qn; i += BT) sh.ce.tc[i] = Cn;
        __syncthreads();
        if (tid < Tn) {
            const int s = src_idx[b*Tn + tid];
            sh.ce.tc[s] = tgt_labels[b*Tn + tgt_idx[b*Tn + tid]];
        }
        __syncthreads();
        for (int q = seg*75 + wrp; q < seg*75 + 75; q += NW) {
            const float* row = pred_logits + (size_t)(b*Qn + q) * (Cn + 1);
            const float x0 = row[lane];
            const float x1 = row[lane + 32];
            const float x2 = (lane < 17) ? row[lane + 64] : -3.4e38f;
            float mx = fmaxf(fmaxf(x0, x1), x2);
            #pragma unroll
            for (int o = 16; o; o >>= 1) mx = fmaxf(mx, __shfl_xor_sync(0xffffffffu, mx, o));
            float se = __expf(x0 - mx) + __expf(x1 - mx) + ((lane < 17) ? __expf(x2 - mx) : 0.f);
            #pragma unroll
            for (int o = 16; o; o >>= 1) se += __shfl_xor_sync(0xffffffffu, se, o);
            if (lane == 0) {
                const int t = sh.ce.tc[q];
                ceN += empty_weight[t] * (mx + __logf(se) - row[t]);
                ceD += empty_weight[t];
            }
        }
    }

    // ======================= all blocks: focal base stream =======================
    float fs = 0.f;
    {
        const int stride = G * BT;
        int i = bid * BT + tid;
        for (; i + 3*stride < HM4; i += 4*stride) {
            const float4 a = __ldcs(&hm4[i]);
            const float4 b = __ldcs(&hm4[i +   stride]);
            const float4 c = __ldcs(&hm4[i + 2*stride]);
            const float4 d = __ldcs(&hm4[i + 3*stride]);
            fs += floss0(a.x) + floss0(a.y) + floss0(a.z) + floss0(a.w);
            fs += floss0(b.x) + floss0(b.y) + floss0(b.z) + floss0(b.w);
            fs += floss0(c.x) + floss0(c.y) + floss0(c.z) + floss0(c.w);
            fs += floss0(d.x) + floss0(d.y) + floss0(d.z) + floss0(d.w);
        }
        for (; i < HM4; i += stride) {
            const float4 a = __ldcs(&hm4[i]);
            fs += floss0(a.x) + floss0(a.y) + floss0(a.z) + floss0(a.w);
        }
    }
    fs += corr;   // block 0 folds its focal corrections into its partial

    // ======================= block reduction of 6 partials =======================
    float v0 = fs, v1 = ceN, v2 = ceD, v3 = myBox, v4 = myBb, v5 = myGi;
    #pragma unroll
    for (int o = 16; o; o >>= 1) {
        v0 += __shfl_xor_sync(0xffffffffu, v0, o);
        v1 += __shfl_xor_sync(0xffffffffu, v1, o);
        v2 += __shfl_xor_sync(0xffffffffu, v2, o);
        v3 += __shfl_xor_sync(0xffffffffu, v3, o);
        v4 += __shfl_xor_sync(0xffffffffu, v4, o);
        v5 += __shfl_xor_sync(0xffffffffu, v5, o);
    }
    if (lane == 0) {
        redf[wrp][0]=v0; redf[wrp][1]=v1; redf[wrp][2]=v2;
        redf[wrp][3]=v3; redf[wrp][4]=v4; redf[wrp][5]=v5;
    }
    __syncthreads();
    if (wrp == 0) {
        v0 = (lane < NW) ? redf[lane][0] : 0.f;
        v1 = (lane < NW) ? redf[lane][1] : 0.f;
        v2 = (lane < NW) ? redf[lane][2] : 0.f;
        v3 = (lane < NW) ? redf[lane][3] : 0.f;
        v4 = (lane < NW) ? redf[lane][4] : 0.f;
        v5 = (lane < NW) ? redf[lane][5] : 0.f;
        #pragma unroll
        for (int o = 16; o; o >>= 1) {
            v0 += __shfl_xor_sync(0xffffffffu, v0, o);
            v1 += __shfl_xor_sync(0xffffffffu, v1, o);
            v2 += __shfl_xor_sync(0xffffffffu, v2, o);
            v3 += __shfl_xor_sync(0xffffffffu, v3, o);
            v4 += __shfl_xor_sync(0xffffffffu, v4, o);
            v5 += __shfl_xor_sync(0xffffffffu, v5, o);
        }
        if (lane == 0) {
            p_hm[bid] = (double)v0;
            p_cn[bid] = (double)v1;
            p_cd[bid] = (double)v2;
            if (bid == 0) { p_box = (double)v3; p_bb = (double)v4; p_gi = (double)v5; }
        }
    }

    // ======================= last-block finalize =======================
    __threadfence();
    if (tid == 0) isLast = (atomicInc(&g_arrive, G - 1) == G - 1);  // wraps to 0
    __syncthreads();
    if (isLast) {
        __threadfence();
        double a = 0.0, b2 = 0.0, c2 = 0.0;
        for (int i = tid; i < G; i += BT) {
            a  += ((volatile double*)p_hm)[i];
            b2 += ((volatile double*)p_cn)[i];
            c2 += ((volatile double*)p_cd)[i];
        }
        #pragma unroll
        for (int o = 16; o; o >>= 1) {
            a  += __shfl_xor_sync(0xffffffffu, a,  o);
            b2 += __shfl_xor_sync(0xffffffffu, b2, o);
            c2 += __shfl_xor_sync(0xffffffffu, c2, o);
        }
        if (lane == 0) { redd[wrp][0] = a; redd[wrp][1] = b2; redd[wrp][2] = c2; }
        __syncthreads();
        if (wrp == 0) {
            a  = (lane < NW) ? redd[lane][0] : 0.0;
            b2 = (lane < NW) ? redd[lane][1] : 0.0;
            c2 = (lane < NW) ? redd[lane][2] : 0.0;
            #pragma unroll
            for (int o = 16; o; o >>= 1) {
                a  += __shfl_xor_sync(0xffffffffu, a,  o);
                b2 += __shfl_xor_sync(0xffffffffu, b2, o);
                c2 += __shfl_xor_sync(0xffffffffu, c2, o);
            }
            if (lane == 0) {
                const double boxc = *((volatile double*)&p_box);
                const double bb   = *((volatile double*)&p_bb);
                const double gi   = *((volatile double*)&p_gi);
                const int    npI  = *((volatile int*)&p_np);
                const double np   = fmax((double)npI, 1.0);
                const float ce   = (float)(b2 / c2);
                const float bbox = (float)(bb / (double)NJ);
                const float giou = (float)(gi / (double)NJ);
                const float hmv  = (float)(a / np);
                const float bl   = (float)(boxc / np);
                const float aux  = hmv + 5.f * bl;
                out[0] = ce;
                out[1] = bbox;
                out[2] = giou;
                out[3] = aux;
                out[4] = ce + 5.f * bbox + 2.f * giou + aux;
            }
        }
    }
}

extern "C" void kernel_launch(void* const* d_in, const int* in_sizes, int n_in,
                              void* d_out, int out_size)
{
    const float* pred_logits  = (const float*)d_in[0];
    const float* pred_boxes   = (const float*)d_in[1];
    const float* heatmap      = (const float*)d_in[2];
    const float* box_map      = (const float*)d_in[3];
    const float* tgt_boxes    = (const float*)d_in[4];
    const int*   tgt_labels   = (const int*)  d_in[5];
    const float* tgt_sizes    = (const float*)d_in[6];
    const int*   src_idx      = (const int*)  d_in[7];
    const int*   tgt_idx      = (const int*)  d_in[8];
    const float* empty_weight = (const float*)d_in[9];

    k_all<<<G, BT>>>(pred_logits, pred_boxes,
                     (const float4*)heatmap, heatmap, box_map, tgt_boxes,
                     tgt_labels, tgt_sizes, src_idx, tgt_idx, empty_weight,
                     (float*)d_out);
}

// round 4
// speedup vs baseline: 1.6542x; 1.2150x over previous
#include <cuda_runtime.h>
#include <math.h>

// Problem shape (fixed by the dataset)
#define Bn 16
#define Qn 300
#define Tn 50
#define Cn 80          // NUM_CLASSES
#define Hn 128
#define Wn 128
#define NJ (Bn*Tn)                 // 800
#define HM_ELEMS (Bn*Cn*Hn*Wn)     // 20,971,520
#define HM4 (HM_ELEMS/4)           // 5,242,880
#define HASHN 2048
#define G  296                     // grid size (2 blocks/SM on 148 SMs)
#define BT 512                     // block size
#define NW (BT/32)                 // 16 warps
#define CHUNK 2048                 // float4 per chunk (4 per thread)
#define NCHUNK (HM4/CHUNK)         // 2560

// Per-block partial slots (overwritten every launch -> no zeroing needed)
__device__ double p_hm[G], p_cn[G], p_cd[G];
__device__ double p_box, p_bb, p_gi;
__device__ int    p_np;
__device__ unsigned g_arrive = 0;   // self-wrapping arrival counter
__device__ unsigned g_chunk  = 0;   // dynamic work ticket (self-wrapping)

struct PrepSh {
    float bfs[NJ][4];
    int   key3s[NJ];
    int   hashA[HASHN];   // dedupe (b,label,gy,gx)
    int   hashBk[HASHN];  // keys   (b,gy,gx)
    int   hashBv[HASHN];  // last-wins winner j per key
    int   snum;
};
struct CeSh { int tc[Qn]; };
union ShU { PrepSh prep; CeSh ce; };

// focal loss at target==0: 0.75 * sigmoid(x)^2 * softplus(x)
// 2-MUFU version: sigmoid via tanh.approx, softplus = -ln(1 - sigmoid) via lg2.approx
__device__ __forceinline__ float floss0(float x) {
    float th;
    asm("tanh.approx.f32 %0, %1;" : "=f"(th) : "f"(0.5f * x));
    const float q = 0.5f - 0.5f * th;   // 1 - sigmoid(x)  = sigmoid(-x)
    const float p = 0.5f + 0.5f * th;   // sigmoid(x)
    float lg;
    asm("lg2.approx.f32 %0, %1;" : "=f"(lg) : "f"(q));
    // 0.75 * p^2 * (-ln q) = -(0.75*ln2) * p^2 * log2(q)
    return -0.51986038f * p * p * lg;
}

__global__ void __launch_bounds__(BT, 2)
k_all(const float*  __restrict__ pred_logits,
      const float*  __restrict__ pred_boxes,
      const float4* __restrict__ hm4,
      const float*  __restrict__ hm,
      const float*  __restrict__ box_map,
      const float*  __restrict__ tgt_boxes,
      const int*    __restrict__ tgt_labels,
      const float*  __restrict__ tgt_sizes,
      const int*    __restrict__ src_idx,
      const int*    __restrict__ tgt_idx,
      const float*  __restrict__ empty_weight,
      float* __restrict__ out)
{
    __shared__ ShU    sh;
    __shared__ float  redf[NW][6];
    __shared__ double redd[NW][3];
    __shared__ bool   isLast;

    const int tid  = threadIdx.x;
    const int bid  = blockIdx.x;
    const int lane = tid & 31, wrp = tid >> 5;

    float corr = 0.f, myBox = 0.f, myBb = 0.f, myGi = 0.f;
    float ceN = 0.f, ceD = 0.f;

    // ======================= block 0: prep =======================
    if (bid == 0) {
        for (int i = tid; i < HASHN; i += BT) {
            sh.prep.hashA[i] = -1; sh.prep.hashBk[i] = -1; sh.prep.hashBv[i] = -1;
        }
        if (tid == 0) sh.prep.snum = 0;
        __syncthreads();

        // phase 1: normalized boxes + hash inserts + focal corrections (exact math)
        for (int j = tid; j < NJ; j += BT) {
            const int b = j / Tn;
            const float h_im = tgt_sizes[b*2 + 0];
            const float w_im = tgt_sizes[b*2 + 1];
            const float4 tb = ((const float4*)tgt_boxes)[j];
            const float x1 = tb.x / w_im, y1 = tb.y / h_im;
            const float x2 = tb.z / w_im, y2 = tb.w / h_im;
            const float cx = 0.5f*(x1 + x2), cy = 0.5f*(y1 + y2);
            sh.prep.bfs[j][0] = cx;      sh.prep.bfs[j][1] = cy;
            sh.prep.bfs[j][2] = x2 - x1; sh.prep.bfs[j][3] = y2 - y1;

            const int lf = tgt_labels[j];
            const int gx = min(max((int)(cx * (float)Wn), 0), Wn - 1);
            const int gy = min(max((int)(cy * (float)Hn), 0), Hn - 1);
            const int key3 = (b*Hn + gy)*Wn + gx;
            sh.prep.key3s[j] = key3;
            const int key4 = ((b*Cn + lf)*Hn + gy)*Wn + gx;

            unsigned hh = ((unsigned)key4 * 2654435761u) & (HASHN - 1);
            bool ins = false;
            for (;;) {
                int prev = atomicCAS(&sh.prep.hashA[hh], -1, key4);
                if (prev == -1) { ins = true; break; }
                if (prev == key4) break;
                hh = (hh + 1) & (HASHN - 1);
            }
            if (ins) {
                const float x   = hm[key4];
                const float ax  = fabsf(x);
                const float l1p = log1pf(expf(-ax));
                const float ce1 = fmaxf(x, 0.f) - x + l1p;   // target = 1
                const float ce0 = fmaxf(x, 0.f) + l1p;       // target = 0
                const float pr  = 1.f / (1.f + expf(-x));
                const float l1  = 0.25f * (1.f - pr) * (1.f - pr) * ce1;
                const float l0  = 0.75f * pr * pr * ce0;
                // subtract the APPROX base term this element contributes in the stream,
                // add the exact positive-target loss
                corr += l1 - floss0(x);
                corr += floss0(x) - l0;   // folds to l1 - l0; kept exact-vs-exact
            }

            hh = ((unsigned)key3 * 2654435761u) & (HASHN - 1);
            int slot;
            for (;;) {
                int prev = atomicCAS(&sh.prep.hashBk[hh], -1, key3);
                if (prev == -1) { atomicAdd(&sh.prep.snum, 1); slot = hh; break; }
                if (prev == key3) { slot = hh; break; }
                hh = (hh + 1) & (HASHN - 1);
            }
            atomicMax(&sh.prep.hashBv[slot], j);
        }
        __syncthreads();

        // phase 2: box_map correction (winners only) + pair L1 + GIoU
        for (int j = tid; j < NJ; j += BT) {
            const int b    = j / Tn;
            const int key3 = sh.prep.key3s[j];
            const int gx   = key3 & (Wn - 1);
            const int gy   = (key3 >> 7) & (Hn - 1);

            unsigned hh = ((unsigned)key3 * 2654435761u) & (HASHN - 1);
            while (sh.prep.hashBk[hh] != key3) hh = (hh + 1) & (HASHN - 1);
            if (sh.prep.hashBv[hh] == j) {
                #pragma unroll
                for (int c = 0; c < 4; c++) {
                    const float bm = box_map[((b*4 + c)*Hn + gy)*Wn + gx];
                    myBox += fabsf(bm - sh.prep.bfs[j][c]);
                }
            }

            const int si = src_idx[j];
            const int ti = tgt_idx[j];
            const float4 sb = ((const float4*)pred_boxes)[b*Qn + si];
            const float s0 = sb.x, s1 = sb.y, s2 = sb.z, s3 = sb.w;
            const float* mb = sh.prep.bfs[b*Tn + ti];
            const float m0 = mb[0], m1 = mb[1], m2 = mb[2], m3 = mb[3];

            myBb += fabsf(s0-m0) + fabsf(s1-m1) + fabsf(s2-m2) + fabsf(s3-m3);

            const float ax1 = s0 - 0.5f*s2, ay1 = s1 - 0.5f*s3;
            const float ax2 = s0 + 0.5f*s2, ay2 = s1 + 0.5f*s3;
            const float bx1 = m0 - 0.5f*m2, by1 = m1 - 0.5f*m3;
            const float bx2 = m0 + 0.5f*m2, by2 = m1 + 0.5f*m3;
            const float area_a = (ax2-ax1)*(ay2-ay1);
            const float area_b = (bx2-bx1)*(by2-by1);
            const float iw = fmaxf(fminf(ax2,bx2) - fmaxf(ax1,bx1), 0.f);
            const float ih = fmaxf(fminf(ay2,by2) - fmaxf(ay1,by1), 0.f);
            const float inter = iw*ih;
            const float uni   = area_a + area_b - inter;
            const float iou   = inter / uni;
            const float cw_   = fmaxf(fmaxf(ax2,bx2) - fminf(ax1,bx1), 0.f);
            const float ch_   = fmaxf(fmaxf(ay2,by2) - fminf(ay1,by1), 0.f);
            const float ac    = cw_ * ch_;
            myGi += 1.f - (iou - (ac - uni)/ac);
        }
        if (tid == 0) p_np = sh.prep.snum;
    }
    // ======================= blocks 1..64: weighted CE =======================
    else if (bid <= 64) {
        const int idx = bid - 1;
        const int b   = idx >> 2;
        const int seg = idx & 3;
        for (int i = tid; i < Qn; i += BT) sh.ce.tc[i] = Cn;
        __syncthreads();
        if (tid < Tn) {
            const int s = src_idx[b*Tn + tid];
            sh.ce.tc[s] = tgt_labels[b*Tn + tgt_idx[b*Tn + tid]];
        }
        __syncthreads();
        for (int q = seg*75 + wrp; q < seg*75 + 75; q += NW) {
            const float* row = pred_logits + (size_t)(b*Qn + q) * (Cn + 1);
            const float x0 = row[lane];
            const float x1 = row[lane + 32];
            const float x2 = (lane < 17) ? row[lane + 64] : -3.4e38f;
            float mx = fmaxf(fmaxf(x0, x1), x2);
            #pragma unroll
            for (int o = 16; o; o >>= 1) mx = fmaxf(mx, __shfl_xor_sync(0xffffffffu, mx, o));
            float se = __expf(x0 - mx) + __expf(x1 - mx) + ((lane < 17) ? __expf(x2 - mx) : 0.f);
            #pragma unroll
            for (int o = 16; o; o >>= 1) se += __shfl_xor_sync(0xffffffffu, se, o);
            if (lane == 0) {
                const int t = sh.ce.tc[q];
                ceN += empty_weight[t] * (mx + __logf(se) - row[t]);
                ceD += empty_weight[t];
            }
        }
    }

    // ============ all blocks: focal base stream (dynamic chunks) ============
    // Each grab = CHUNK float4 = 4 float4 per thread. Ticket counter wraps at
    // NCHUNK+G-1: every block fails exactly one grab -> counter returns to 0
    // deterministically each launch/replay.
    float fs = 0.f;
    __shared__ unsigned s_c;
    for (;;) {
        if (tid == 0) s_c = atomicInc(&g_chunk, (unsigned)(NCHUNK + G - 1));
        __syncthreads();
        const unsigned c = s_c;
        __syncthreads();
        if (c >= NCHUNK) break;
        const int base = (int)c * CHUNK + tid;
        const float4 a = __ldcs(&hm4[base]);
        const float4 b = __ldcs(&hm4[base +   BT]);
        const float4 d = __ldcs(&hm4[base + 2*BT]);
        const float4 e = __ldcs(&hm4[base + 3*BT]);
        fs += floss0(a.x) + floss0(a.y) + floss0(a.z) + floss0(a.w);
        fs += floss0(b.x) + floss0(b.y) + floss0(b.z) + floss0(b.w);
        fs += floss0(d.x) + floss0(d.y) + floss0(d.z) + floss0(d.w);
        fs += floss0(e.x) + floss0(e.y) + floss0(e.z) + floss0(e.w);
    }
    fs += corr;   // block 0 folds its focal corrections into its partial

    // ======================= block reduction of 6 partials =======================
    float v0 = fs, v1 = ceN, v2 = ceD, v3 = myBox, v4 = myBb, v5 = myGi;
    #pragma unroll
    for (int o = 16; o; o >>= 1) {
        v0 += __shfl_xor_sync(0xffffffffu, v0, o);
        v1 += __shfl_xor_sync(0xffffffffu, v1, o);
        v2 += __shfl_xor_sync(0xffffffffu, v2, o);
        v3 += __shfl_xor_sync(0xffffffffu, v3, o);
        v4 += __shfl_xor_sync(0xffffffffu, v4, o);
        v5 += __shfl_xor_sync(0xffffffffu, v5, o);
    }
    if (lane == 0) {
        redf[wrp][0]=v0; redf[wrp][1]=v1; redf[wrp][2]=v2;
        redf[wrp][3]=v3; redf[wrp][4]=v4; redf[wrp][5]=v5;
    }
    __syncthreads();
    if (wrp == 0) {
        v0 = (lane < NW) ? redf[lane][0] : 0.f;
        v1 = (lane < NW) ? redf[lane][1] : 0.f;
        v2 = (lane < NW) ? redf[lane][2] : 0.f;
        v3 = (lane < NW) ? redf[lane][3] : 0.f;
        v4 = (lane < NW) ? redf[lane][4] : 0.f;
        v5 = (lane < NW) ? redf[lane][5] : 0.f;
        #pragma unroll
        for (int o = 16; o; o >>= 1) {
            v0 += __shfl_xor_sync(0xffffffffu, v0, o);
            v1 += __shfl_xor_sync(0xffffffffu, v1, o);
            v2 += __shfl_xor_sync(0xffffffffu, v2, o);
            v3 += __shfl_xor_sync(0xffffffffu, v3, o);
            v4 += __shfl_xor_sync(0xffffffffu, v4, o);
            v5 += __shfl_xor_sync(0xffffffffu, v5, o);
        }
        if (lane == 0) {
            p_hm[bid] = (double)v0;
            p_cn[bid] = (double)v1;
            p_cd[bid] = (double)v2;
            if (bid == 0) { p_box = (double)v3; p_bb = (double)v4; p_gi = (double)v5; }
        }
    }

    // ======================= last-block finalize =======================
    __threadfence();
    if (tid == 0) isLast = (atomicInc(&g_arrive, G - 1) == G - 1);  // wraps to 0
    __syncthreads();
    if (isLast) {
        __threadfence();
        double a = 0.0, b2 = 0.0, c2 = 0.0;
        for (int i = tid; i < G; i += BT) {
            a  += ((volatile double*)p_hm)[i];
            b2 += ((volatile double*)p_cn)[i];
            c2 += ((volatile double*)p_cd)[i];
        }
        #pragma unroll
        for (int o = 16; o; o >>= 1) {
            a  += __shfl_xor_sync(0xffffffffu, a,  o);
            b2 += __shfl_xor_sync(0xffffffffu, b2, o);
            c2 += __shfl_xor_sync(0xffffffffu, c2, o);
        }
        if (lane == 0) { redd[wrp][0] = a; redd[wrp][1] = b2; redd[wrp][2] = c2; }
        __syncthreads();
        if (wrp == 0) {
            a  = (lane < NW) ? redd[lane][0] : 0.0;
            b2 = (lane < NW) ? redd[lane][1] : 0.0;
            c2 = (lane < NW) ? redd[lane][2] : 0.0;
            #pragma unroll
            for (int o = 16; o; o >>= 1) {
                a  += __shfl_xor_sync(0xffffffffu, a,  o);
                b2 += __shfl_xor_sync(0xffffffffu, b2, o);
                c2 += __shfl_xor_sync(0xffffffffu, c2, o);
            }
            if (lane == 0) {
                const double boxc = *((volatile double*)&p_box);
                const double bb   = *((volatile double*)&p_bb);
                const double gi   = *((volatile double*)&p_gi);
                const int    npI  = *((volatile int*)&p_np);
                const double np   = fmax((double)npI, 1.0);
                const float ce   = (float)(b2 / c2);
                const float bbox = (float)(bb / (double)NJ);
                const float giou = (float)(gi / (double)NJ);
                const float hmv  = (float)(a / np);
                const float bl   = (float)(boxc / np);
                const float aux  = hmv + 5.f * bl;
                out[0] = ce;
                out[1] = bbox;
                out[2] = giou;
                out[3] = aux;
                out[4] = ce + 5.f * bbox + 2.f * giou + aux;
            }
        }
    }
}

extern "C" void kernel_launch(void* const* d_in, const int* in_sizes, int n_in,
                              void* d_out, int out_size)
{
    const float* pred_logits  = (const float*)d_in[0];
    const float* pred_boxes   = (const float*)d_in[1];
    const float* heatmap      = (const float*)d_in[2];
    const float* box_map      = (const float*)d_in[3];
    const float* tgt_boxes    = (const float*)d_in[4];
    const int*   tgt_labels   = (const int*)  d_in[5];
    const float* tgt_sizes    = (const float*)d_in[6];
    const int*   src_idx      = (const int*)  d_in[7];
    const int*   tgt_idx      = (const int*)  d_in[8];
    const float* empty_weight = (const float*)d_in[9];

    k_all<<<G, BT>>>(pred_logits, pred_boxes,
                     (const float4*)heatmap, heatmap, box_map, tgt_boxes,
                     tgt_labels, tgt_sizes, src_idx, tgt_idx, empty_weight,
                     (float*)d_out);
}